// round 15
// baseline (speedup 1.0000x reference)
#include <cuda_runtime.h>
#include <math.h>
#include <float.h>

#define H 2048
#define S 2048
#define V 50257
#define GRID 148
#define TPB 1024
#define NTHR (GRID * TPB)

// ---------------- device scratch (allocation-free rule) ----------------
__device__ __align__(16) float g_partT[2048 * 152]; // [col][148 partials, pad 152]
__device__ __align__(16) float g_cat[2 * H];        // [embedded ; attn_applied]
__device__ __align__(16) float g_x[H];              // relu(comb output)
__device__ __align__(16) float g_gh[3 * H];         // w_hh @ h0 dots
__device__ __align__(16) float g_gx[3 * H];         // w_ih @ x dots
__device__ __align__(16) float g_h[H];              // h_new
__device__ __align__(16) float g_logits[V];
__device__ float g_pm[GRID], g_ps[GRID];            // per-CTA lse partials
__device__ int g_bar_cnt[8];                        // zero-init; monotonic across replays
__device__ int g_bar_flag[8];

__device__ __forceinline__ float warp_sum(float v) {
    #pragma unroll
    for (int o = 16; o > 0; o >>= 1) v += __shfl_xor_sync(0xffffffffu, v, o);
    return v;
}

// Grid-wide barrier (CG-style). Replay-safe: generation = old/GRID, no resets.
// Requires all GRID CTAs co-resident (grid=148 = 1 CTA/SM, single wave).
__device__ __forceinline__ void grid_bar(int i) {
    __syncthreads();
    if (threadIdx.x == 0) {
        __threadfence();
        int old = atomicAdd(&g_bar_cnt[i], 1);
        int gen = old / GRID;
        if ((old % GRID) == GRID - 1) {
            atomicExch(&g_bar_flag[i], gen + 1);
        } else {
            while (atomicAdd(&g_bar_flag[i], 0) <= gen) __nanosleep(64);
        }
        __threadfence();
    }
    __syncthreads();
}

// Single-row K=2048 dot (proven k6 shape): 2 phases of 8-deep __ldcs batches.
__device__ __forceinline__ float dot2048_cs(const float4* __restrict__ wr,
                                            const float4* __restrict__ xs, int lane) {
    float acc = 0.f;
    #pragma unroll
    for (int ph = 0; ph < 2; ++ph) {
        float4 wb[8];
        #pragma unroll
        for (int i = 0; i < 8; ++i) wb[i] = __ldcs(wr + lane + 32 * (ph * 8 + i));
        #pragma unroll
        for (int i = 0; i < 8; ++i) {
            float4 x = xs[lane + 32 * (ph * 8 + i)];
            acc += wb[i].x * x.x + wb[i].y * x.y + wb[i].z * x.z + wb[i].w * x.w;
        }
    }
    return acc;
}

// ===== THE kernel: entire decoder step in ONE launch, grid 148 x 1024 =====
__global__ __launch_bounds__(TPB, 1) void kAll(
        const float* __restrict__ w_hh,   const float* __restrict__ hprev,
        const float* __restrict__ enc,    const float* __restrict__ emb,
        const int*   __restrict__ input_id,
        const float* __restrict__ comb_w, const float* __restrict__ comb_b,
        const float* __restrict__ w_ih,
        const float* __restrict__ b_ih,   const float* __restrict__ b_hh,
        const float* __restrict__ out_w,  const float* __restrict__ out_b,
        float* __restrict__ out, int out_size) {
    __shared__ __align__(16) float smem[2 * H + 64];
    int b = blockIdx.x, tid = threadIdx.x;
    int wpid = tid >> 5, lane = tid & 31;
    // Balanced 2048-item partition used by P1 rows / P2 cols / P3 rows:
    int start14 = b * 13 + min(b, 124);              // 124 CTAs x 14 + 24 x 13
    int cnt14 = 13 + (b < 124 ? 1 : 0);

    // ---- P1: enc column-sum partials (ALL CTAs, 13-14 rows each) + embed (CTA 0,1)
    {
        if (b < 2) {
            int j = b * 1024 + tid;
            g_cat[j] = emb[(size_t)input_id[0] * H + j];
        }
        int c0 = tid, c1 = tid + 1024;
        float s0 = 0.f, s1 = 0.f, s2 = 0.f, s3 = 0.f;
        int i = 0;
        for (; i + 2 <= cnt14; i += 2) {
            const float* r0 = enc + (size_t)(start14 + i) * H;
            const float* r1 = enc + (size_t)(start14 + i + 1) * H;
            s0 += r0[c0]; s1 += r0[c1];
            s2 += r1[c0]; s3 += r1[c1];
        }
        if (i < cnt14) {
            const float* r0 = enc + (size_t)(start14 + i) * H;
            s0 += r0[c0]; s1 += r0[c1];
        }
        g_partT[(size_t)c0 * 152 + b] = s0 + s2;     // transposed partials
        g_partT[(size_t)c1 * 152 + b] = s1 + s3;
    }
    grid_bar(0);

    // ---- P2: finish cat (ALL CTAs; warp per column, contiguous 148 reads)
    if (wpid < cnt14) {
        int col = start14 + wpid;
        const float* p = g_partT + (size_t)col * 152;
        float s = 0.f;
        #pragma unroll
        for (int c = lane; c < 148; c += 32) s += p[c];   // 4-5 per lane
        s = warp_sum(s);
        if (lane == 0) g_cat[H + col] = s;
    }
    grid_bar(1);

    // ---- P3: x = relu(comb_w @ cat + comb_b). 2 warps/row K-split, 13-14 rows/CTA.
    {
        ((float4*)smem)[tid] = ((const float4*)g_cat)[tid];   // 4096 floats exact
        __syncthreads();
        float* part = smem + 2 * H;
        int wpair = wpid >> 1, half = wpid & 1;
        if (wpair < cnt14) {
            int row = start14 + wpair;
            float d = warp_sum(dot2048_cs(
                (const float4*)(comb_w + (size_t)row * 2 * H + (size_t)half * H),
                (const float4*)(smem + half * H), lane));
            if (lane == 0) part[wpid] = d;
        }
        __syncthreads();
        if (tid < cnt14) {
            int r = start14 + tid;
            g_x[r] = fmaxf(part[2 * tid] + part[2 * tid + 1] + comb_b[r], 0.f);
        }
        __syncthreads();
    }
    grid_bar(2);

    // ---- P4: MERGED w_ih + w_hh GEMV. 12288 rows over 4736 warps = uniform
    // 2-3 rows/warp. rows [0,6144) = w_ih vs g_x; [6144,12288) = w_hh vs hprev.
    {
        if (tid < 512) ((float4*)smem)[tid] = ((const float4*)g_x)[tid];
        else           ((float4*)smem)[tid] = ((const float4*)hprev)[tid - 512];
        __syncthreads();
        int gw = wpid * GRID + b;                    // 0..4735
        for (int row = gw; row < 12288; row += 4736) {
            const float* w;
            const float4* xv;
            float* dst;
            if (row < 6144) {
                w = w_ih + (size_t)row * H;
                xv = (const float4*)smem;
                dst = g_gx + row;
            } else {
                w = w_hh + (size_t)(row - 6144) * H;
                xv = (const float4*)(smem + H);
                dst = g_gh + (row - 6144);
            }
            float d = warp_sum(dot2048_cs((const float4*)w, xv, lane));
            if (lane == 0) *dst = d;
        }
        __syncthreads();
    }
    grid_bar(3);

    // ---- P5 (redundant per CTA): GRU gates -> h in smem[0..2048); CTA0 -> g_h.
    {
        #pragma unroll
        for (int c = 0; c < 2; ++c) {
            int j = c * 1024 + tid;
            float pre_r = g_gx[j]     + b_ih[j]     + g_gh[j]     + b_hh[j];
            float pre_z = g_gx[H + j] + b_ih[H + j] + g_gh[H + j] + b_hh[H + j];
            float r = 1.f / (1.f + expf(-pre_r));
            float z = 1.f / (1.f + expf(-pre_z));
            float n = tanhf(g_gx[2 * H + j] + b_ih[2 * H + j]
                            + r * (g_gh[2 * H + j] + b_hh[2 * H + j]));
            float hv = (1.f - z) * n + z * hprev[j];
            smem[j] = hv;
            if (b == 0) g_h[j] = hv;
        }
        __syncthreads();
    }

    // ---- P6: logits = out_w @ h + out_b. Proven mapping, h already in smem.
    {
        for (int row = wpid * GRID + b; row < V; row += 4736) {
            float d = warp_sum(dot2048_cs((const float4*)(out_w + (size_t)row * H),
                                          (const float4*)smem, lane));
            if (lane == 0) g_logits[row] = d + out_b[row];
        }
    }
    grid_bar(4);

    // ---- P7: per-CTA lse partial (CTAs 0..49 have data; rest pad)
    {
        float* sm = smem;
        float* ss = smem + 1024;
        __syncthreads();                             // smem reuse after P6 reads
        int i = b * TPB + tid;
        float m = (i < V) ? g_logits[i] : -FLT_MAX;
        float s = (i < V) ? 1.f : 0.f;
        sm[tid] = m; ss[tid] = s;
        __syncthreads();
        for (int o = 512; o > 0; o >>= 1) {
            if (tid < o) {
                float m2 = sm[tid + o], s2 = ss[tid + o];
                float nm = fmaxf(sm[tid], m2);
                ss[tid] = ss[tid] * expf(sm[tid] - nm) + s2 * expf(m2 - nm);
                sm[tid] = nm;
            }
            __syncthreads();
        }
        if (tid == 0) { g_pm[b] = sm[0]; g_ps[b] = ss[0]; }
    }
    grid_bar(5);

    // ---- P7b (redundant per CTA): warp 0 combines 148 partials -> smem shift
    if (wpid == 0) {
        float m = -FLT_MAX, s = 0.f;
        #pragma unroll
        for (int c = 0; c < 5; ++c) {
            int idx = c * 32 + lane;
            if (idx < GRID) {
                float m2 = g_pm[idx], s2 = g_ps[idx];
                float nm = fmaxf(m, m2);
                s = s * expf(m - nm) + s2 * expf(m2 - nm);
                m = nm;
            }
        }
        #pragma unroll
        for (int o = 16; o > 0; o >>= 1) {
            float m2 = __shfl_xor_sync(0xffffffffu, m, o);
            float s2 = __shfl_xor_sync(0xffffffffu, s, o);
            float nm = fmaxf(m, m2);
            s = s * expf(m - nm) + s2 * expf(m2 - nm);
            m = nm;
        }
        if (lane == 0) smem[0] = m + logf(s);
    }
    __syncthreads();

    // ---- P8: write outputs: log_probs (V) | h_new (H) | attn_weights=1 (S)
    {
        float shift = smem[0];
        for (int i = b * TPB + tid; i < out_size; i += NTHR) {
            if (i < V)            out[i] = g_logits[i] - shift;
            else if (i < V + H)   out[i] = g_h[i - V];
            else                  out[i] = 1.0f;
        }
    }
}

extern "C" void kernel_launch(void* const* d_in, const int* in_sizes, int n_in,
                              void* d_out, int out_size) {
    const int*   input_id = (const int*)  d_in[0];
    const float* hidden   = (const float*)d_in[1];   // (1,1,H)
    const float* enc      = (const float*)d_in[2];   // (S,H)
    const float* emb      = (const float*)d_in[3];   // (V,H)
    // d_in[4], d_in[5]: attn_w / attn_b — provably dead (softmax over singleton)
    const float* comb_w   = (const float*)d_in[6];
    const float* comb_b   = (const float*)d_in[7];
    const float* w_ih     = (const float*)d_in[8];
    const float* w_hh     = (const float*)d_in[9];
    const float* b_ih     = (const float*)d_in[10];
    const float* b_hh     = (const float*)d_in[11];
    const float* out_w    = (const float*)d_in[12];
    const float* out_b    = (const float*)d_in[13];
    float* out = (float*)d_out;

    kAll<<<GRID, TPB>>>(w_hh, hidden, enc, emb, input_id,
                        comb_w, comb_b, w_ih, b_ih, b_hh,
                        out_w, out_b, out, out_size);
}